// round 8
// baseline (speedup 1.0000x reference)
#include <cuda_runtime.h>
#include <math.h>

// ---------------- problem constants ----------------
#define B_TOTAL   16384
#define NSLOT     32
#define SDIM      64
#define HID       128
#define NKNOWN    9
#define NITER     3

#define PV_OFF    0
#define SLOTS_OFF (B_TOTAL*NKNOWN)                       // 147456
#define FREE_OFF  (B_TOTAL*NKNOWN + B_TOTAL*NSLOT*SDIM)  // 33701888

// scratch: gi[b][192] (upd == v for every slot since attn collapses to exactly 1.0)
__device__ float g_gi[(size_t)B_TOTAL * 192];

typedef unsigned long long u64;
union F2 { float f[2]; u64 u; };

__device__ __forceinline__ u64 pk2(float x) {
    u64 r; asm("mov.b64 %0, {%1, %1};" : "=l"(r) : "f"(x)); return r;
}
__device__ __forceinline__ void fma2(u64 &a, u64 b, u64 c) {
    asm("fma.rn.f32x2 %0, %1, %2, %0;" : "+l"(a) : "l"(b), "l"(c));
}
__device__ __forceinline__ float sigm_f(float x) { return 1.0f / (1.0f + __expf(-x)); }
__device__ __forceinline__ float tanh_f(float x) {
    float ax = fabsf(x);
    float t = __expf(-2.0f * ax);
    float r = __fdividef(1.0f - t, 1.0f + t);
    return copysignf(r, x);
}
__device__ __forceinline__ float gelu_f(float x) { return 0.5f * x * (1.0f + erff(x * 0.70710678118654752440f)); }

// ================= Kernel A2: per-batch x -> LN -> v -> gi (weights staged in smem) =================
#define SMEMA_FLOATS 36304

__global__ void __launch_bounds__(512, 1) kA2(
    const float* __restrict__ ws, const float* __restrict__ Wi, const float* __restrict__ bi,
    const float* __restrict__ g_in, const float* __restrict__ b_in,
    const float* __restrict__ Wv, const float* __restrict__ bv,
    const float* __restrict__ Wih, const float* __restrict__ bih)
{
    extern __shared__ float sa[];
    float* s_wi  = sa;
    float* s_wv  = sa + 16384;
    float* s_wih = sa + 20480;
    float* s_bi  = sa + 32768;
    float* s_bv  = sa + 32832;
    float* s_gin = sa + 32896;
    float* s_bin = sa + 32960;
    float* s_bih = sa + 33024;
    float* s_in  = sa + 33216;
    float* s_x   = sa + 35264;
    float* s_v   = sa + 35776;
    float* s_red = sa + 36288;

    int tid = threadIdx.x;
    int g = tid >> 6;
    int lane = tid & 63;
    size_t b = (size_t)blockIdx.x * 8 + g;

    for (int i = tid; i < 16384 / 4; i += 512) ((float4*)s_wi)[i]  = ((const float4*)Wi)[i];
    for (int i = tid; i < 4096 / 4;  i += 512) ((float4*)s_wv)[i]  = ((const float4*)Wv)[i];
    for (int i = tid; i < 12288 / 4; i += 512) ((float4*)s_wih)[i] = ((const float4*)Wih)[i];
    if (tid < 64)  s_bi[tid]  = bi[tid];
    if (tid >= 64  && tid < 128) s_bv[tid - 64]   = bv[tid - 64];
    if (tid >= 128 && tid < 192) s_gin[tid - 128] = g_in[tid - 128];
    if (tid >= 192 && tid < 256) s_bin[tid - 192] = b_in[tid - 192];
    if (tid >= 256 && tid < 448) s_bih[tid - 256] = bih[tid - 256];

    {
        const float4* src = (const float4*)(ws + (size_t)blockIdx.x * 8 * 256);
        for (int i = tid; i < 2048 / 4; i += 512) ((float4*)s_in)[i] = src[i];
    }
    __syncthreads();

    const float* in_g = s_in + g * 256;

    float acc = s_bi[lane];
    #pragma unroll 4
    for (int i = 0; i < 256; i++) acc += in_g[i] * s_wi[i * 64 + lane];

    float v = acc;
    #pragma unroll
    for (int o = 16; o; o >>= 1) v += __shfl_down_sync(0xffffffffu, v, o);
    if ((lane & 31) == 0) s_red[g * 2 + (lane >> 5)] = v;
    __syncthreads();
    float mu = (s_red[g * 2] + s_red[g * 2 + 1]) * (1.0f / 64.0f);
    __syncthreads();
    float dv = acc - mu;
    float vv = dv * dv;
    #pragma unroll
    for (int o = 16; o; o >>= 1) vv += __shfl_down_sync(0xffffffffu, vv, o);
    if ((lane & 31) == 0) s_red[g * 2 + (lane >> 5)] = vv;
    __syncthreads();
    float var = (s_red[g * 2] + s_red[g * 2 + 1]) * (1.0f / 64.0f);
    float inv = rsqrtf(var + 1e-5f);
    s_x[g * 64 + lane] = dv * inv * s_gin[lane] + s_bin[lane];
    __syncthreads();

    const float* x_g = s_x + g * 64;
    float vacc = s_bv[lane];
    #pragma unroll 4
    for (int d = 0; d < 64; d++) vacc += x_g[d] * s_wv[d * 64 + lane];
    s_v[g * 64 + lane] = vacc;
    __syncthreads();

    const float* v_g = s_v + g * 64;
    #pragma unroll
    for (int j = lane; j < 192; j += 64) {
        float a = s_bih[j];
        #pragma unroll 4
        for (int d = 0; d < 64; d++) a += v_g[d] * s_wih[d * 192 + j];
        g_gi[b * 192 + j] = a;
    }
}

// ================= Kernel Z: zero free_act accumulators =================
__global__ void kZ(float* __restrict__ out)
{
    int i = threadIdx.x;
    if (i < NSLOT - NKNOWN) out[FREE_OFF + i] = 0.0f;
}

// ================= Kernel B: 512 threads = 8 batch x 32 slots x 2 halves =================
// thread owns 32 contiguous dims [half*32, half*32+32) of its slot.
// partner thread = lane ^ 1 (same warp).
#define SMEMB_FLOATS 47360

__global__ void __launch_bounds__(512, 1) kB(
    const float* __restrict__ eps, const float* __restrict__ mu0, const float* __restrict__ sg0,
    const float* __restrict__ Whh, const float* __restrict__ bhh,
    const float* __restrict__ W1, const float* __restrict__ b1,
    const float* __restrict__ W2, const float* __restrict__ b2,
    const float* __restrict__ gm, const float* __restrict__ bm,
    const float* __restrict__ Wh1, const float* __restrict__ bh1,
    const float* __restrict__ Wh2, const float* __restrict__ bh2,
    float* __restrict__ out)
{
    extern __shared__ float sm[];
    float* s_whh  = sm;
    float* s_w1   = sm + 12288;
    float* s_w2   = sm + 20480;
    float* s_bhh  = sm + 28672;
    float* s_b1   = sm + 28864;
    float* s_b2   = sm + 28992;
    float* s_gm   = sm + 29056;
    float* s_bm   = sm + 29120;
    float* s_gi   = sm + 29184;
    float* s_prev = sm + 30720;   // 256 slots * stride 65

    int tid = threadIdx.x;

    for (int i = tid; i < 12288 / 4; i += 512) ((float4*)s_whh)[i] = ((const float4*)Whh)[i];
    for (int i = tid; i < 8192 / 4;  i += 512) ((float4*)s_w1)[i]  = ((const float4*)W1)[i];
    for (int i = tid; i < 8192 / 4;  i += 512) ((float4*)s_w2)[i]  = ((const float4*)W2)[i];
    if (tid < 192) s_bhh[tid] = bhh[tid];
    if (tid >= 256 && tid < 384) s_b1[tid - 256]  = b1[tid - 256];
    if (tid >= 192 && tid < 256) s_b2[tid - 192] = b2[tid - 192];
    if (tid >= 384 && tid < 448) s_gm[tid - 384] = gm[tid - 384];
    if (tid >= 448 && tid < 512) s_bm[tid - 448] = bm[tid - 448];
    {
        const float* gsrc = g_gi + (size_t)blockIdx.x * 8 * 192;
        for (int i = tid; i < 1536; i += 512) s_gi[i] = gsrc[i];
    }

    int bb   = tid >> 6;          // batch group 0..7
    int s    = (tid & 63) >> 1;   // slot 0..31
    int half = tid & 1;           // 0 or 1: dims [half*32, half*32+32)
    size_t b = (size_t)blockIdx.x * 8 + bb;
    int pbase = (tid >> 1) * 65;  // slot row in s_prev
    int hb = half * 32;           // my dim base

    // slots init: mu + sigma * eps (my half only)
    {
        const float4* ep = (const float4*)(eps + (b * NSLOT + s) * SDIM + hb);
        const float4* m4 = (const float4*)(mu0 + (size_t)s * SDIM + hb);
        const float4* g4 = (const float4*)(sg0 + (size_t)s * SDIM + hb);
        #pragma unroll
        for (int q = 0; q < 8; q++) {
            float4 e = ep[q], m = m4[q], sg = g4[q];
            s_prev[pbase + hb + 4 * q + 0] = m.x + sg.x * e.x;
            s_prev[pbase + hb + 4 * q + 1] = m.y + sg.y * e.y;
            s_prev[pbase + hb + 4 * q + 2] = m.z + sg.z * e.z;
            s_prev[pbase + hb + 4 * q + 3] = m.w + sg.w * e.w;
        }
    }
    __syncthreads();

    const float* gi = s_gi + bb * 192;
    F2 st[16];   // my 32 dims packed: st[m] = dims {hb+2m, hb+2m+1}

    for (int it = 0; it < NITER; ++it) {
        // ---- pass 1: r = sigmoid(gi_r + prev@Whh[:, hb:hb+32] + bhh_r) ----
        #pragma unroll
        for (int q = 0; q < 16; q++) {
            st[q].f[0] = s_bhh[hb + 2 * q]     + gi[hb + 2 * q];
            st[q].f[1] = s_bhh[hb + 2 * q + 1] + gi[hb + 2 * q + 1];
        }
        #pragma unroll 2
        for (int d = 0; d < 64; d++) {
            u64 p2 = pk2(s_prev[pbase + d]);
            const ulonglong2* w = (const ulonglong2*)(s_whh + d * 192 + hb);
            #pragma unroll
            for (int q = 0; q < 8; q++) {
                ulonglong2 ww = w[q];
                fma2(st[2 * q].u,     ww.x, p2);
                fma2(st[2 * q + 1].u, ww.y, p2);
            }
        }
        #pragma unroll
        for (int q = 0; q < 16; q++) {
            st[q].f[0] = sigm_f(st[q].f[0]);
            st[q].f[1] = sigm_f(st[q].f[1]);
        }

        // ---- pass 2: z, n, new state — 2 chunks of 16 cols ----
        #pragma unroll
        for (int cb = 0; cb < 2; cb++) {
            F2 az[8], an[8];
            #pragma unroll
            for (int qq = 0; qq < 8; qq++) {
                int jg = hb + cb * 16 + 2 * qq;
                az[qq].f[0] = s_bhh[64 + jg]     + gi[64 + jg];
                az[qq].f[1] = s_bhh[64 + jg + 1] + gi[64 + jg + 1];
                an[qq].f[0] = s_bhh[128 + jg];        // gi_n added after r*(...)
                an[qq].f[1] = s_bhh[128 + jg + 1];
            }
            #pragma unroll 2
            for (int d = 0; d < 64; d++) {
                u64 p2 = pk2(s_prev[pbase + d]);
                const ulonglong2* wz = (const ulonglong2*)(s_whh + d * 192 + 64  + hb + cb * 16);
                const ulonglong2* wn = (const ulonglong2*)(s_whh + d * 192 + 128 + hb + cb * 16);
                #pragma unroll
                for (int q = 0; q < 4; q++) {
                    ulonglong2 a = wz[q];
                    fma2(az[2 * q].u,     a.x, p2);
                    fma2(az[2 * q + 1].u, a.y, p2);
                    ulonglong2 c = wn[q];
                    fma2(an[2 * q].u,     c.x, p2);
                    fma2(an[2 * q + 1].u, c.y, p2);
                }
            }
            #pragma unroll
            for (int jj = 0; jj < 16; jj++) {
                int j = cb * 16 + jj;      // local 0..31
                int jg = hb + j;
                float z  = sigm_f(az[jj >> 1].f[jj & 1]);
                float aa = an[jj >> 1].f[jj & 1];
                float r  = st[j >> 1].f[j & 1];
                float n  = tanh_f(gi[128 + jg] + r * aa);
                float pr = s_prev[pbase + jg];
                st[j >> 1].f[j & 1] = (1.0f - z) * n + z * pr;
            }
        }

        // ---- LayerNorm over 64 (pairwise shfl with partner) ----
        float lsum = 0.0f;
        #pragma unroll
        for (int q = 0; q < 16; q++) lsum += st[q].f[0] + st[q].f[1];
        lsum += __shfl_xor_sync(0xffffffffu, lsum, 1);
        float mu = lsum * (1.0f / 64.0f);
        float lvar = 0.0f;
        #pragma unroll
        for (int q = 0; q < 16; q++) {
            float d0 = st[q].f[0] - mu, d1 = st[q].f[1] - mu;
            lvar += d0 * d0 + d1 * d1;
        }
        lvar += __shfl_xor_sync(0xffffffffu, lvar, 1);
        float inv = rsqrtf(lvar * (1.0f / 64.0f) + 1e-5f);
        #pragma unroll
        for (int q = 0; q < 16; q++) {
            s_prev[pbase + hb + 2 * q]     = (st[q].f[0] - mu) * inv * s_gm[hb + 2 * q]     + s_bm[hb + 2 * q];
            s_prev[pbase + hb + 2 * q + 1] = (st[q].f[1] - mu) * inv * s_gm[hb + 2 * q + 1] + s_bm[hb + 2 * q + 1];
        }
        __syncwarp();
        #pragma unroll
        for (int q = 0; q < 16; q++) {
            st[q].f[0] += s_b2[hb + 2 * q];
            st[q].f[1] += s_b2[hb + 2 * q + 1];
        }

        // ---- MLP: my hidden cols [half*64, half*64+64) in 2 chunks of 32 ----
        #pragma unroll
        for (int cb = 0; cb < 2; cb++) {
            int hbase = half * 64 + cb * 32;
            F2 ah[16];
            #pragma unroll
            for (int qq = 0; qq < 16; qq++) {
                ah[qq].f[0] = s_b1[hbase + 2 * qq];
                ah[qq].f[1] = s_b1[hbase + 2 * qq + 1];
            }
            #pragma unroll 2
            for (int d = 0; d < 64; d++) {
                u64 p2 = pk2(s_prev[pbase + d]);
                const ulonglong2* w = (const ulonglong2*)(s_w1 + d * 128 + hbase);
                #pragma unroll
                for (int q = 0; q < 8; q++) {
                    ulonglong2 a = w[q];
                    fma2(ah[2 * q].u,     a.x, p2);
                    fma2(ah[2 * q + 1].u, a.y, p2);
                }
            }
            float garr[32];
            #pragma unroll
            for (int hh = 0; hh < 32; hh++) garr[hh] = gelu_f(ah[hh >> 1].f[hh & 1]);
            // W2: each hidden pair (mine + partner's same-index) accumulates into my 32 dims
            #pragma unroll
            for (int hh = 0; hh < 32; hh++) {
                int myH = hbase + hh;
                int otH = myH ^ 64;    // partner's hidden index at same hh
                float ga = garr[hh];
                float gb = __shfl_xor_sync(0xffffffffu, ga, 1);
                u64 g2a = pk2(ga), g2b = pk2(gb);
                const ulonglong2* w2a = (const ulonglong2*)(s_w2 + myH * 64 + hb);
                const ulonglong2* w2b = (const ulonglong2*)(s_w2 + otH * 64 + hb);
                #pragma unroll
                for (int q = 0; q < 8; q++) {
                    ulonglong2 wa = w2a[q];
                    fma2(st[2 * q].u,     wa.x, g2a);
                    fma2(st[2 * q + 1].u, wa.y, g2a);
                    ulonglong2 wb = w2b[q];
                    fma2(st[2 * q].u,     wb.x, g2b);
                    fma2(st[2 * q + 1].u, wb.y, g2b);
                }
            }
        }
        #pragma unroll
        for (int q = 0; q < 16; q++) {
            s_prev[pbase + hb + 2 * q]     = st[q].f[0];
            s_prev[pbase + hb + 2 * q + 1] = st[q].f[1];
        }
        __syncwarp();
    }

    // ---- write final slots (my half) ----
    {
        float4* o = (float4*)(out + SLOTS_OFF + (b * NSLOT + s) * SDIM + hb);
        #pragma unroll
        for (int q = 0; q < 8; q++) {
            o[q] = make_float4(st[2 * q].f[0], st[2 * q].f[1],
                               st[2 * q + 1].f[0], st[2 * q + 1].f[1]);
        }
    }

    // ---- free_act: pairwise sum before smem reuse (full mask, all lanes) ----
    float sq = 0.0f;
    #pragma unroll
    for (int q = 0; q < 16; q++) sq += st[q].f[0] * st[q].f[0] + st[q].f[1] * st[q].f[1];
    sq += __shfl_xor_sync(0xffffffffu, sq, 1);
    float freeval = sqrtf(sq) * (1.0f / (float)B_TOTAL);

    // ---- head (reuse weight smem) + block free_act reduction ----
    __syncthreads();
    float* s_hw1  = sm;           // 18432 floats
    float* s_hb1  = sm + 18432;   // 288
    float* s_hw2  = sm + 18720;   // 288
    float* s_hb2  = sm + 19008;   // 9
    float* s_free = sm + 19072;   // 23
    for (int i = tid; i < 18432 / 4; i += 512) ((float4*)s_hw1)[i] = ((const float4*)Wh1)[i];
    if (tid < 288) { s_hb1[tid] = bh1[tid]; s_hw2[tid] = Wh2[tid]; }   // FIXED: full 288 staged
    if (tid >= 288 && tid < 297) s_hb2[tid - 288] = bh2[tid - 288];
    if (tid >= 320 && tid < 343) s_free[tid - 320] = 0.0f;             // FIXED: in-range zeroing
    __syncthreads();

    // head computed by ALL threads (clamped k keeps indices legal), warp-uniform shfl
    {
        int k = (s < NKNOWN) ? s : (NKNOWN - 1);
        int hh0 = half * 16;       // my 16 of 32 hidden units
        F2 ha[8];
        #pragma unroll
        for (int q = 0; q < 8; q++) {
            ha[q].f[0] = s_hb1[k * 32 + hh0 + 2 * q];
            ha[q].f[1] = s_hb1[k * 32 + hh0 + 2 * q + 1];
        }
        #pragma unroll 2
        for (int d = 0; d < 64; d++) {
            u64 p2 = pk2(s_prev[pbase + d]);
            const ulonglong2* w = (const ulonglong2*)(s_hw1 + k * 2048 + d * 32 + hh0);
            #pragma unroll
            for (int q = 0; q < 4; q++) {
                ulonglong2 a = w[q];
                fma2(ha[2 * q].u,     a.x, p2);
                fma2(ha[2 * q + 1].u, a.y, p2);
            }
        }
        float a2 = 0.0f;
        #pragma unroll
        for (int q = 0; q < 8; q++) {
            a2 += gelu_f(ha[q].f[0]) * s_hw2[k * 32 + hh0 + 2 * q];
            a2 += gelu_f(ha[q].f[1]) * s_hw2[k * 32 + hh0 + 2 * q + 1];
        }
        a2 += __shfl_xor_sync(0xffffffffu, a2, 1);   // full-warp uniform
        if (half == 0) {
            if (s < NKNOWN) out[PV_OFF + b * NKNOWN + s] = sigm_f(a2 + s_hb2[s]);
            else            atomicAdd(s_free + (s - NKNOWN), freeval);
        }
    }
    __syncthreads();
    if (tid < NSLOT - NKNOWN) atomicAdd(out + FREE_OFF + tid, s_free[tid]);
}

// ================= launch =================
extern "C" void kernel_launch(void* const* d_in, const int* in_sizes, int n_in,
                              void* d_out, int out_size)
{
    const float* ws   = (const float*)d_in[0];
    const float* eps  = (const float*)d_in[1];
    const float* mu0  = (const float*)d_in[2];
    const float* sg0  = (const float*)d_in[3];
    const float* Wi   = (const float*)d_in[4];
    const float* bi   = (const float*)d_in[5];
    // d_in[6..9] = Wk, bk, Wq, bq : dead (attn == 1.0 exactly)
    const float* Wv   = (const float*)d_in[10];
    const float* bv   = (const float*)d_in[11];
    const float* Wih  = (const float*)d_in[12];
    const float* bih  = (const float*)d_in[13];
    const float* Whh  = (const float*)d_in[14];
    const float* bhh  = (const float*)d_in[15];
    const float* W1   = (const float*)d_in[16];
    const float* b1   = (const float*)d_in[17];
    const float* W2   = (const float*)d_in[18];
    const float* b2   = (const float*)d_in[19];
    const float* g_in = (const float*)d_in[20];
    const float* b_in = (const float*)d_in[21];
    // d_in[22..23] = g_sl, b_sl : dead
    const float* gm   = (const float*)d_in[24];
    const float* bm   = (const float*)d_in[25];
    const float* Wh1  = (const float*)d_in[26];
    const float* bh1  = (const float*)d_in[27];
    const float* Wh2  = (const float*)d_in[28];
    const float* bh2  = (const float*)d_in[29];
    float* out = (float*)d_out;

    size_t smemA = (size_t)SMEMA_FLOATS * sizeof(float);
    size_t smemB = (size_t)SMEMB_FLOATS * sizeof(float);
    cudaFuncSetAttribute(kA2, cudaFuncAttributeMaxDynamicSharedMemorySize, (int)smemA);
    cudaFuncSetAttribute(kB,  cudaFuncAttributeMaxDynamicSharedMemorySize, (int)smemB);

    kA2<<<B_TOTAL / 8, 512, smemA>>>(ws, Wi, bi, g_in, b_in, Wv, bv, Wih, bih);
    kZ<<<1, 32>>>(out);
    kB<<<B_TOTAL / 8, 512, smemB>>>(eps, mu0, sg0, Whh, bhh, W1, b1, W2, b2,
                                    gm, bm, Wh1, bh1, Wh2, bh2, out);
}

// round 9
// speedup vs baseline: 1.1776x; 1.1776x over previous
#include <cuda_runtime.h>
#include <math.h>

// ---------------- problem constants ----------------
#define B_TOTAL   16384
#define NSLOT     32
#define SDIM      64
#define HID       128
#define NKNOWN    9
#define NITER     3

#define PV_OFF    0
#define SLOTS_OFF (B_TOTAL*NKNOWN)                       // 147456
#define FREE_OFF  (B_TOTAL*NKNOWN + B_TOTAL*NSLOT*SDIM)  // 33701888

// scratch: gi[b][192] (upd == v for every slot since attn collapses to exactly 1.0)
__device__ float g_gi[(size_t)B_TOTAL * 192];

__device__ __forceinline__ float sigm_f(float x) { return 1.0f / (1.0f + __expf(-x)); }
__device__ __forceinline__ float tanh_f(float x) {
    float ax = fabsf(x);
    float t = __expf(-2.0f * ax);
    float r = __fdividef(1.0f - t, 1.0f + t);
    return copysignf(r, x);
}
__device__ __forceinline__ float gelu_f(float x) { return 0.5f * x * (1.0f + erff(x * 0.70710678118654752440f)); }

// ================= Kernel A2: per-batch x -> LN -> v -> gi (weights staged in smem) =================
#define SMEMA_FLOATS 36304

__global__ void __launch_bounds__(512, 1) kA2(
    const float* __restrict__ ws, const float* __restrict__ Wi, const float* __restrict__ bi,
    const float* __restrict__ g_in, const float* __restrict__ b_in,
    const float* __restrict__ Wv, const float* __restrict__ bv,
    const float* __restrict__ Wih, const float* __restrict__ bih)
{
    extern __shared__ float sa[];
    float* s_wi  = sa;
    float* s_wv  = sa + 16384;
    float* s_wih = sa + 20480;
    float* s_bi  = sa + 32768;
    float* s_bv  = sa + 32832;
    float* s_gin = sa + 32896;
    float* s_bin = sa + 32960;
    float* s_bih = sa + 33024;
    float* s_in  = sa + 33216;
    float* s_x   = sa + 35264;
    float* s_v   = sa + 35776;
    float* s_red = sa + 36288;

    int tid = threadIdx.x;
    int g = tid >> 6;
    int lane = tid & 63;
    size_t b = (size_t)blockIdx.x * 8 + g;

    for (int i = tid; i < 16384 / 4; i += 512) ((float4*)s_wi)[i]  = ((const float4*)Wi)[i];
    for (int i = tid; i < 4096 / 4;  i += 512) ((float4*)s_wv)[i]  = ((const float4*)Wv)[i];
    for (int i = tid; i < 12288 / 4; i += 512) ((float4*)s_wih)[i] = ((const float4*)Wih)[i];
    if (tid < 64)  s_bi[tid]  = bi[tid];
    if (tid >= 64  && tid < 128) s_bv[tid - 64]   = bv[tid - 64];
    if (tid >= 128 && tid < 192) s_gin[tid - 128] = g_in[tid - 128];
    if (tid >= 192 && tid < 256) s_bin[tid - 192] = b_in[tid - 192];
    if (tid >= 256 && tid < 448) s_bih[tid - 256] = bih[tid - 256];

    {
        const float4* src = (const float4*)(ws + (size_t)blockIdx.x * 8 * 256);
        for (int i = tid; i < 2048 / 4; i += 512) ((float4*)s_in)[i] = src[i];
    }
    __syncthreads();

    const float* in_g = s_in + g * 256;

    float acc = s_bi[lane];
    #pragma unroll 4
    for (int i = 0; i < 256; i++) acc += in_g[i] * s_wi[i * 64 + lane];

    float v = acc;
    #pragma unroll
    for (int o = 16; o; o >>= 1) v += __shfl_down_sync(0xffffffffu, v, o);
    if ((lane & 31) == 0) s_red[g * 2 + (lane >> 5)] = v;
    __syncthreads();
    float mu = (s_red[g * 2] + s_red[g * 2 + 1]) * (1.0f / 64.0f);
    __syncthreads();
    float dv = acc - mu;
    float vv = dv * dv;
    #pragma unroll
    for (int o = 16; o; o >>= 1) vv += __shfl_down_sync(0xffffffffu, vv, o);
    if ((lane & 31) == 0) s_red[g * 2 + (lane >> 5)] = vv;
    __syncthreads();
    float var = (s_red[g * 2] + s_red[g * 2 + 1]) * (1.0f / 64.0f);
    float inv = rsqrtf(var + 1e-5f);
    s_x[g * 64 + lane] = dv * inv * s_gin[lane] + s_bin[lane];
    __syncthreads();

    const float* x_g = s_x + g * 64;
    float vacc = s_bv[lane];
    #pragma unroll 4
    for (int d = 0; d < 64; d++) vacc += x_g[d] * s_wv[d * 64 + lane];
    s_v[g * 64 + lane] = vacc;
    __syncthreads();

    const float* v_g = s_v + g * 64;
    #pragma unroll
    for (int j = lane; j < 192; j += 64) {
        float a = s_bih[j];
        #pragma unroll 4
        for (int d = 0; d < 64; d++) a += v_g[d] * s_wih[d * 192 + j];
        g_gi[b * 192 + j] = a;
    }
}

// ================= Kernel Z: zero free_act accumulators =================
__global__ void kZ(float* __restrict__ out)
{
    int i = threadIdx.x;
    if (i < NSLOT - NKNOWN) out[FREE_OFF + i] = 0.0f;
}

// ================= Kernel B: 512 threads = 16 batch groups x 32 slots, 1 thread/slot =================
// scalar FFMA datapath (R4-proven); prev state in thread-local array (coalesced LDL/STL)
// smem (floats):
//   0      s_whh 12288
//   12288  s_w1   8192
//   20480  s_w2   8192
//   28672  s_bhh   192
//   28864  s_b1    128
//   28992  s_b2     64
//   29056  s_gm     64
//   29120  s_bm     64
//   29184  s_gi   3072   (16 groups x 192)
// total 32256 floats = 129024 B
#define SMEMB_FLOATS 32256

__global__ void __launch_bounds__(512, 1) kB(
    const float* __restrict__ eps, const float* __restrict__ mu0, const float* __restrict__ sg0,
    const float* __restrict__ Whh, const float* __restrict__ bhh,
    const float* __restrict__ W1, const float* __restrict__ b1,
    const float* __restrict__ W2, const float* __restrict__ b2,
    const float* __restrict__ gm, const float* __restrict__ bm,
    const float* __restrict__ Wh1, const float* __restrict__ bh1,
    const float* __restrict__ Wh2, const float* __restrict__ bh2,
    float* __restrict__ out)
{
    extern __shared__ float sm[];
    float* s_whh  = sm;
    float* s_w1   = sm + 12288;
    float* s_w2   = sm + 20480;
    float* s_bhh  = sm + 28672;
    float* s_b1   = sm + 28864;
    float* s_b2   = sm + 28992;
    float* s_gm   = sm + 29056;
    float* s_bm   = sm + 29120;
    float* s_gi   = sm + 29184;

    int tid = threadIdx.x;

    for (int i = tid; i < 12288 / 4; i += 512) ((float4*)s_whh)[i] = ((const float4*)Whh)[i];
    for (int i = tid; i < 8192 / 4;  i += 512) ((float4*)s_w1)[i]  = ((const float4*)W1)[i];
    for (int i = tid; i < 8192 / 4;  i += 512) ((float4*)s_w2)[i]  = ((const float4*)W2)[i];
    if (tid < 192) s_bhh[tid] = bhh[tid];
    if (tid < 128) s_b1[tid]  = b1[tid];
    if (tid < 64) { s_b2[tid] = b2[tid]; s_gm[tid] = gm[tid]; s_bm[tid] = bm[tid]; }
    {
        const float* gsrc = g_gi + (size_t)blockIdx.x * 16 * 192;
        for (int i = tid; i < 3072; i += 512) s_gi[i] = gsrc[i];
    }

    int bb = tid >> 5, s = tid & 31;
    size_t b = (size_t)blockIdx.x * 16 + bb;

    float pv[SDIM];   // per-thread slot state; dynamic-indexed -> local memory, coalesced

    // slots init: mu + sigma * eps
    {
        const float4* ep = (const float4*)(eps + (b * NSLOT + s) * SDIM);
        const float4* m4 = (const float4*)(mu0 + (size_t)s * SDIM);
        const float4* g4 = (const float4*)(sg0 + (size_t)s * SDIM);
        #pragma unroll
        for (int q = 0; q < 16; q++) {
            float4 e = ep[q], m = m4[q], sg = g4[q];
            pv[4 * q + 0] = m.x + sg.x * e.x;
            pv[4 * q + 1] = m.y + sg.y * e.y;
            pv[4 * q + 2] = m.z + sg.z * e.z;
            pv[4 * q + 3] = m.w + sg.w * e.w;
        }
    }
    __syncthreads();

    const float* gi = s_gi + bb * 192;
    float rbuf[64];

    for (int it = 0; it < NITER; ++it) {
        // ---- pass 1: r = sigmoid(gi_r + prev@Whh[:,0:64] + bhh_r) ----
        #pragma unroll
        for (int j = 0; j < 64; j++) rbuf[j] = s_bhh[j] + gi[j];
        #pragma unroll 2
        for (int d = 0; d < 64; d++) {
            float p = pv[d];
            const float4* w = (const float4*)(s_whh + d * 192);
            #pragma unroll
            for (int q = 0; q < 16; q++) {
                float4 ww = w[q];
                rbuf[4 * q + 0] += p * ww.x; rbuf[4 * q + 1] += p * ww.y;
                rbuf[4 * q + 2] += p * ww.z; rbuf[4 * q + 3] += p * ww.w;
            }
        }
        #pragma unroll
        for (int j = 0; j < 64; j++) rbuf[j] = sigm_f(rbuf[j]);

        // ---- pass 2: z, n, new state (j-chunks of 16; rbuf holds r then new state) ----
        #pragma unroll
        for (int jb = 0; jb < 4; jb++) {
            float az[16], an[16];
            #pragma unroll
            for (int jj = 0; jj < 16; jj++) {
                int j = jb * 16 + jj;
                az[jj] = s_bhh[64 + j] + gi[64 + j];
                an[jj] = s_bhh[128 + j];           // gi_n added after r*(dot+bhh_n)
            }
            #pragma unroll 2
            for (int d = 0; d < 64; d++) {
                float p = pv[d];
                const float4* wz = (const float4*)(s_whh + d * 192 + 64 + jb * 16);
                const float4* wn = (const float4*)(s_whh + d * 192 + 128 + jb * 16);
                #pragma unroll
                for (int q = 0; q < 4; q++) {
                    float4 a = wz[q];
                    az[4 * q + 0] += p * a.x; az[4 * q + 1] += p * a.y;
                    az[4 * q + 2] += p * a.z; az[4 * q + 3] += p * a.w;
                    float4 c = wn[q];
                    an[4 * q + 0] += p * c.x; an[4 * q + 1] += p * c.y;
                    an[4 * q + 2] += p * c.z; an[4 * q + 3] += p * c.w;
                }
            }
            #pragma unroll
            for (int jj = 0; jj < 16; jj++) {
                int j = jb * 16 + jj;
                float z = sigm_f(az[jj]);
                float n = tanh_f(gi[128 + j] + rbuf[j] * an[jj]);
                float pr = pv[j];
                rbuf[j] = (1.0f - z) * n + z * pr;
            }
        }

        // ---- LayerNorm + MLP residual ----
        float mu = 0.0f;
        #pragma unroll
        for (int j = 0; j < 64; j++) mu += rbuf[j];
        mu *= (1.0f / 64.0f);
        float var = 0.0f;
        #pragma unroll
        for (int j = 0; j < 64; j++) { float d = rbuf[j] - mu; var += d * d; }
        var *= (1.0f / 64.0f);
        float inv = rsqrtf(var + 1e-5f);
        #pragma unroll
        for (int d = 0; d < 64; d++) pv[d] = (rbuf[d] - mu) * inv * s_gm[d] + s_bm[d];
        #pragma unroll
        for (int j = 0; j < 64; j++) rbuf[j] += s_b2[j];

        for (int mb = 0; mb < 8; mb++) {
            float ah[16];
            #pragma unroll
            for (int jj = 0; jj < 16; jj++) ah[jj] = s_b1[mb * 16 + jj];
            #pragma unroll 2
            for (int d = 0; d < 64; d++) {
                float p = pv[d];
                const float4* w = (const float4*)(s_w1 + d * 128 + mb * 16);
                #pragma unroll
                for (int q = 0; q < 4; q++) {
                    float4 a = w[q];
                    ah[4 * q + 0] += p * a.x; ah[4 * q + 1] += p * a.y;
                    ah[4 * q + 2] += p * a.z; ah[4 * q + 3] += p * a.w;
                }
            }
            #pragma unroll
            for (int jj = 0; jj < 16; jj++) {
                float g = gelu_f(ah[jj]);
                const float4* w2 = (const float4*)(s_w2 + (mb * 16 + jj) * 64);
                #pragma unroll
                for (int q = 0; q < 16; q++) {
                    float4 ww = w2[q];
                    rbuf[4 * q + 0] += g * ww.x; rbuf[4 * q + 1] += g * ww.y;
                    rbuf[4 * q + 2] += g * ww.z; rbuf[4 * q + 3] += g * ww.w;
                }
            }
        }
        #pragma unroll
        for (int d = 0; d < 64; d++) pv[d] = rbuf[d];
    }

    // ---- write final slots ----
    {
        float4* o = (float4*)(out + SLOTS_OFF + (b * NSLOT + s) * SDIM);
        #pragma unroll
        for (int q = 0; q < 16; q++)
            o[q] = make_float4(rbuf[4 * q], rbuf[4 * q + 1], rbuf[4 * q + 2], rbuf[4 * q + 3]);
    }

    // ---- free_act partial (per thread) ----
    float freeval = 0.0f;
    if (s >= NKNOWN) {
        float sq = 0.0f;
        #pragma unroll
        for (int d = 0; d < 64; d++) sq += rbuf[d] * rbuf[d];
        freeval = sqrtf(sq) * (1.0f / (float)B_TOTAL);
    }

    // ---- head (reuse weight smem for Wh1 etc.) + block-level free_act reduction ----
    __syncthreads();
    float* s_hw1  = sm;           // 18432 floats (overlaps s_whh+s_w1, dead now)
    float* s_hb1  = sm + 18432;   // 288
    float* s_hw2  = sm + 18720;   // 288
    float* s_hb2  = sm + 19008;   // 9
    float* s_free = sm + 19072;   // 23
    for (int i = tid; i < 18432 / 4; i += 512) ((float4*)s_hw1)[i] = ((const float4*)Wh1)[i];
    if (tid < 288) { s_hb1[tid] = bh1[tid]; s_hw2[tid] = Wh2[tid]; }
    if (tid >= 288 && tid < 297) s_hb2[tid - 288] = bh2[tid - 288];
    if (tid >= 320 && tid < 343) s_free[tid - 320] = 0.0f;
    __syncthreads();

    if (s < NKNOWN) {
        int k = s;
        float ha[32];
        #pragma unroll
        for (int h = 0; h < 32; h++) ha[h] = s_hb1[k * 32 + h];
        #pragma unroll 2
        for (int d = 0; d < 64; d++) {
            float p = pv[d];
            const float4* w = (const float4*)(s_hw1 + k * 2048 + d * 32);
            #pragma unroll
            for (int q = 0; q < 8; q++) {
                float4 a = w[q];
                ha[4 * q + 0] += p * a.x; ha[4 * q + 1] += p * a.y;
                ha[4 * q + 2] += p * a.z; ha[4 * q + 3] += p * a.w;
            }
        }
        float a2 = s_hb2[k];
        #pragma unroll
        for (int h = 0; h < 32; h++) a2 += gelu_f(ha[h]) * s_hw2[k * 32 + h];
        out[PV_OFF + b * NKNOWN + k] = sigm_f(a2);
    } else {
        atomicAdd(s_free + (s - NKNOWN), freeval);
    }
    __syncthreads();
    if (tid < NSLOT - NKNOWN) atomicAdd(out + FREE_OFF + tid, s_free[tid]);
}

// ================= launch =================
extern "C" void kernel_launch(void* const* d_in, const int* in_sizes, int n_in,
                              void* d_out, int out_size)
{
    const float* ws   = (const float*)d_in[0];
    const float* eps  = (const float*)d_in[1];
    const float* mu0  = (const float*)d_in[2];
    const float* sg0  = (const float*)d_in[3];
    const float* Wi   = (const float*)d_in[4];
    const float* bi   = (const float*)d_in[5];
    // d_in[6..9] = Wk, bk, Wq, bq : dead (attn == 1.0 exactly)
    const float* Wv   = (const float*)d_in[10];
    const float* bv   = (const float*)d_in[11];
    const float* Wih  = (const float*)d_in[12];
    const float* bih  = (const float*)d_in[13];
    const float* Whh  = (const float*)d_in[14];
    const float* bhh  = (const float*)d_in[15];
    const float* W1   = (const float*)d_in[16];
    const float* b1   = (const float*)d_in[17];
    const float* W2   = (const float*)d_in[18];
    const float* b2   = (const float*)d_in[19];
    const float* g_in = (const float*)d_in[20];
    const float* b_in = (const float*)d_in[21];
    // d_in[22..23] = g_sl, b_sl : dead
    const float* gm   = (const float*)d_in[24];
    const float* bm   = (const float*)d_in[25];
    const float* Wh1  = (const float*)d_in[26];
    const float* bh1  = (const float*)d_in[27];
    const float* Wh2  = (const float*)d_in[28];
    const float* bh2  = (const float*)d_in[29];
    float* out = (float*)d_out;

    size_t smemA = (size_t)SMEMA_FLOATS * sizeof(float);
    size_t smemB = (size_t)SMEMB_FLOATS * sizeof(float);
    cudaFuncSetAttribute(kA2, cudaFuncAttributeMaxDynamicSharedMemorySize, (int)smemA);
    cudaFuncSetAttribute(kB,  cudaFuncAttributeMaxDynamicSharedMemorySize, (int)smemB);

    kA2<<<B_TOTAL / 8, 512, smemA>>>(ws, Wi, bi, g_in, b_in, Wv, bv, Wih, bih);
    kZ<<<1, 32>>>(out);
    kB<<<B_TOTAL / 16, 512, smemB>>>(eps, mu0, sg0, Whh, bhh, W1, b1, W2, b2,
                                     gm, bm, Wh1, bh1, Wh2, bh2, out);
}

// round 10
// speedup vs baseline: 1.5428x; 1.3101x over previous
#include <cuda_runtime.h>
#include <math.h>

// ---------------- problem constants ----------------
#define B_TOTAL   16384
#define NSLOT     32
#define SDIM      64
#define HID       128
#define NKNOWN    9
#define NITER     3

#define PV_OFF    0
#define SLOTS_OFF (B_TOTAL*NKNOWN)                       // 147456
#define FREE_OFF  (B_TOTAL*NKNOWN + B_TOTAL*NSLOT*SDIM)  // 33701888

// scratch: gi[b][192] (upd == v for every slot since attn collapses to exactly 1.0)
__device__ float g_gi[(size_t)B_TOTAL * 192];

__device__ __forceinline__ float sigm_f(float x) { return 1.0f / (1.0f + __expf(-x)); }
__device__ __forceinline__ float tanh_f(float x) {
    float ax = fabsf(x);
    float t = __expf(-2.0f * ax);
    float r = __fdividef(1.0f - t, 1.0f + t);
    return copysignf(r, x);
}
__device__ __forceinline__ float gelu_f(float x) { return 0.5f * x * (1.0f + erff(x * 0.70710678118654752440f)); }

// ================= Kernel A2: per-batch x -> LN -> v -> gi (weights staged in smem) =================
#define SMEMA_FLOATS 36304

__global__ void __launch_bounds__(512, 1) kA2(
    const float* __restrict__ ws, const float* __restrict__ Wi, const float* __restrict__ bi,
    const float* __restrict__ g_in, const float* __restrict__ b_in,
    const float* __restrict__ Wv, const float* __restrict__ bv,
    const float* __restrict__ Wih, const float* __restrict__ bih)
{
    extern __shared__ float sa[];
    float* s_wi  = sa;
    float* s_wv  = sa + 16384;
    float* s_wih = sa + 20480;
    float* s_bi  = sa + 32768;
    float* s_bv  = sa + 32832;
    float* s_gin = sa + 32896;
    float* s_bin = sa + 32960;
    float* s_bih = sa + 33024;
    float* s_in  = sa + 33216;
    float* s_x   = sa + 35264;
    float* s_v   = sa + 35776;
    float* s_red = sa + 36288;

    int tid = threadIdx.x;
    int g = tid >> 6;
    int lane = tid & 63;
    size_t b = (size_t)blockIdx.x * 8 + g;

    for (int i = tid; i < 16384 / 4; i += 512) ((float4*)s_wi)[i]  = ((const float4*)Wi)[i];
    for (int i = tid; i < 4096 / 4;  i += 512) ((float4*)s_wv)[i]  = ((const float4*)Wv)[i];
    for (int i = tid; i < 12288 / 4; i += 512) ((float4*)s_wih)[i] = ((const float4*)Wih)[i];
    if (tid < 64)  s_bi[tid]  = bi[tid];
    if (tid >= 64  && tid < 128) s_bv[tid - 64]   = bv[tid - 64];
    if (tid >= 128 && tid < 192) s_gin[tid - 128] = g_in[tid - 128];
    if (tid >= 192 && tid < 256) s_bin[tid - 192] = b_in[tid - 192];
    if (tid >= 256 && tid < 448) s_bih[tid - 256] = bih[tid - 256];

    {
        const float4* src = (const float4*)(ws + (size_t)blockIdx.x * 8 * 256);
        for (int i = tid; i < 2048 / 4; i += 512) ((float4*)s_in)[i] = src[i];
    }
    __syncthreads();

    const float* in_g = s_in + g * 256;

    float acc = s_bi[lane];
    #pragma unroll 4
    for (int i = 0; i < 256; i++) acc += in_g[i] * s_wi[i * 64 + lane];

    float v = acc;
    #pragma unroll
    for (int o = 16; o; o >>= 1) v += __shfl_down_sync(0xffffffffu, v, o);
    if ((lane & 31) == 0) s_red[g * 2 + (lane >> 5)] = v;
    __syncthreads();
    float mu = (s_red[g * 2] + s_red[g * 2 + 1]) * (1.0f / 64.0f);
    __syncthreads();
    float dv = acc - mu;
    float vv = dv * dv;
    #pragma unroll
    for (int o = 16; o; o >>= 1) vv += __shfl_down_sync(0xffffffffu, vv, o);
    if ((lane & 31) == 0) s_red[g * 2 + (lane >> 5)] = vv;
    __syncthreads();
    float var = (s_red[g * 2] + s_red[g * 2 + 1]) * (1.0f / 64.0f);
    float inv = rsqrtf(var + 1e-5f);
    s_x[g * 64 + lane] = dv * inv * s_gin[lane] + s_bin[lane];
    __syncthreads();

    const float* x_g = s_x + g * 64;
    float vacc = s_bv[lane];
    #pragma unroll 4
    for (int d = 0; d < 64; d++) vacc += x_g[d] * s_wv[d * 64 + lane];
    s_v[g * 64 + lane] = vacc;
    __syncthreads();

    const float* v_g = s_v + g * 64;
    #pragma unroll
    for (int j = lane; j < 192; j += 64) {
        float a = s_bih[j];
        #pragma unroll 4
        for (int d = 0; d < 64; d++) a += v_g[d] * s_wih[d * 192 + j];
        g_gi[b * 192 + j] = a;
    }
}

// ================= Kernel Z: zero free_act accumulators =================
__global__ void kZ(float* __restrict__ out)
{
    int i = threadIdx.x;
    if (i < NSLOT - NKNOWN) out[FREE_OFF + i] = 0.0f;
}

// ================= Kernel B: 384 threads = 12 batch groups x 32 slots, 1 thread/slot =================
// scalar FFMA datapath (R4-proven), prev in smem; 12 warps/SM, reg cap 170
// smem (floats):
//   0      s_whh 12288
//   12288  s_w1   8192
//   20480  s_w2   8192
//   28672  s_bhh   192
//   28864  s_b1    128
//   28992  s_b2     64
//   29056  s_gm     64
//   29120  s_bm     64
//   29184  s_gi   2304   (12 x 192)
//   31488  s_prev 24960  (384 x 65, conflict-free)
// total 56448 floats = 225792 B
#define SMEMB_FLOATS 56448
#define GROUPS_B 12

__global__ void __launch_bounds__(384, 1) kB(
    const float* __restrict__ eps, const float* __restrict__ mu0, const float* __restrict__ sg0,
    const float* __restrict__ Whh, const float* __restrict__ bhh,
    const float* __restrict__ W1, const float* __restrict__ b1,
    const float* __restrict__ W2, const float* __restrict__ b2,
    const float* __restrict__ gm, const float* __restrict__ bm,
    const float* __restrict__ Wh1, const float* __restrict__ bh1,
    const float* __restrict__ Wh2, const float* __restrict__ bh2,
    float* __restrict__ out)
{
    extern __shared__ float sm[];
    float* s_whh  = sm;
    float* s_w1   = sm + 12288;
    float* s_w2   = sm + 20480;
    float* s_bhh  = sm + 28672;
    float* s_b1   = sm + 28864;
    float* s_b2   = sm + 28992;
    float* s_gm   = sm + 29056;
    float* s_bm   = sm + 29120;
    float* s_gi   = sm + 29184;
    float* s_prev = sm + 31488;

    int tid = threadIdx.x;

    for (int i = tid; i < 12288 / 4; i += 384) ((float4*)s_whh)[i] = ((const float4*)Whh)[i];
    for (int i = tid; i < 8192 / 4;  i += 384) ((float4*)s_w1)[i]  = ((const float4*)W1)[i];
    for (int i = tid; i < 8192 / 4;  i += 384) ((float4*)s_w2)[i]  = ((const float4*)W2)[i];
    if (tid < 192) s_bhh[tid] = bhh[tid];
    if (tid < 128) s_b1[tid]  = b1[tid];
    if (tid < 64) { s_b2[tid] = b2[tid]; s_gm[tid] = gm[tid]; s_bm[tid] = bm[tid]; }
    {
        // guarded gi stage (last block is partial)
        size_t gbase = (size_t)blockIdx.x * GROUPS_B * 192;
        for (int i = tid; i < GROUPS_B * 192; i += 384)
            if (gbase + i < (size_t)B_TOTAL * 192) s_gi[i] = g_gi[gbase + i];
    }

    int bb = tid >> 5, s = tid & 31;
    size_t b = (size_t)blockIdx.x * GROUPS_B + bb;
    bool valid = (b < (size_t)B_TOTAL);
    int pbase = tid * 65;

    // slots init: mu + sigma * eps (guarded)
    if (valid) {
        const float4* ep = (const float4*)(eps + (b * NSLOT + s) * SDIM);
        const float4* m4 = (const float4*)(mu0 + (size_t)s * SDIM);
        const float4* g4 = (const float4*)(sg0 + (size_t)s * SDIM);
        #pragma unroll
        for (int q = 0; q < 16; q++) {
            float4 e = ep[q], m = m4[q], sg = g4[q];
            s_prev[pbase + 4 * q + 0] = m.x + sg.x * e.x;
            s_prev[pbase + 4 * q + 1] = m.y + sg.y * e.y;
            s_prev[pbase + 4 * q + 2] = m.z + sg.z * e.z;
            s_prev[pbase + 4 * q + 3] = m.w + sg.w * e.w;
        }
    } else {
        #pragma unroll
        for (int q = 0; q < 64; q++) s_prev[pbase + q] = 0.0f;   // keep garbage-free (no NaN traps)
    }
    __syncthreads();

    const float* gi = s_gi + bb * 192;
    float rbuf[64];

    for (int it = 0; it < NITER; ++it) {
        // ---- pass 1: r = sigmoid(gi_r + prev@Whh[:,0:64] + bhh_r) ----
        #pragma unroll
        for (int j = 0; j < 64; j++) rbuf[j] = s_bhh[j] + gi[j];
        #pragma unroll 2
        for (int d = 0; d < 64; d++) {
            float p = s_prev[pbase + d];
            const float4* w = (const float4*)(s_whh + d * 192);
            #pragma unroll
            for (int q = 0; q < 16; q++) {
                float4 ww = w[q];
                rbuf[4 * q + 0] += p * ww.x; rbuf[4 * q + 1] += p * ww.y;
                rbuf[4 * q + 2] += p * ww.z; rbuf[4 * q + 3] += p * ww.w;
            }
        }
        #pragma unroll
        for (int j = 0; j < 64; j++) rbuf[j] = sigm_f(rbuf[j]);

        // ---- pass 2: z, n, new state (j-chunks of 16; rbuf holds r then new state) ----
        #pragma unroll
        for (int jb = 0; jb < 4; jb++) {
            float az[16], an[16];
            #pragma unroll
            for (int jj = 0; jj < 16; jj++) {
                int j = jb * 16 + jj;
                az[jj] = s_bhh[64 + j] + gi[64 + j];
                an[jj] = s_bhh[128 + j];           // gi_n added after r*(dot+bhh_n)
            }
            #pragma unroll 2
            for (int d = 0; d < 64; d++) {
                float p = s_prev[pbase + d];
                const float4* wz = (const float4*)(s_whh + d * 192 + 64 + jb * 16);
                const float4* wn = (const float4*)(s_whh + d * 192 + 128 + jb * 16);
                #pragma unroll
                for (int q = 0; q < 4; q++) {
                    float4 a = wz[q];
                    az[4 * q + 0] += p * a.x; az[4 * q + 1] += p * a.y;
                    az[4 * q + 2] += p * a.z; az[4 * q + 3] += p * a.w;
                    float4 c = wn[q];
                    an[4 * q + 0] += p * c.x; an[4 * q + 1] += p * c.y;
                    an[4 * q + 2] += p * c.z; an[4 * q + 3] += p * c.w;
                }
            }
            #pragma unroll
            for (int jj = 0; jj < 16; jj++) {
                int j = jb * 16 + jj;
                float z = sigm_f(az[jj]);
                float n = tanh_f(gi[128 + j] + rbuf[j] * an[jj]);
                float pr = s_prev[pbase + j];
                rbuf[j] = (1.0f - z) * n + z * pr;
            }
        }

        // ---- LayerNorm + MLP residual ----
        float mu = 0.0f;
        #pragma unroll
        for (int j = 0; j < 64; j++) mu += rbuf[j];
        mu *= (1.0f / 64.0f);
        float var = 0.0f;
        #pragma unroll
        for (int j = 0; j < 64; j++) { float d = rbuf[j] - mu; var += d * d; }
        var *= (1.0f / 64.0f);
        float inv = rsqrtf(var + 1e-5f);
        #pragma unroll
        for (int d = 0; d < 64; d++) s_prev[pbase + d] = (rbuf[d] - mu) * inv * s_gm[d] + s_bm[d];
        #pragma unroll
        for (int j = 0; j < 64; j++) rbuf[j] += s_b2[j];

        for (int mb = 0; mb < 8; mb++) {
            float ah[16];
            #pragma unroll
            for (int jj = 0; jj < 16; jj++) ah[jj] = s_b1[mb * 16 + jj];
            #pragma unroll 2
            for (int d = 0; d < 64; d++) {
                float p = s_prev[pbase + d];
                const float4* w = (const float4*)(s_w1 + d * 128 + mb * 16);
                #pragma unroll
                for (int q = 0; q < 4; q++) {
                    float4 a = w[q];
                    ah[4 * q + 0] += p * a.x; ah[4 * q + 1] += p * a.y;
                    ah[4 * q + 2] += p * a.z; ah[4 * q + 3] += p * a.w;
                }
            }
            #pragma unroll
            for (int jj = 0; jj < 16; jj++) {
                float g = gelu_f(ah[jj]);
                const float4* w2 = (const float4*)(s_w2 + (mb * 16 + jj) * 64);
                #pragma unroll
                for (int q = 0; q < 16; q++) {
                    float4 ww = w2[q];
                    rbuf[4 * q + 0] += g * ww.x; rbuf[4 * q + 1] += g * ww.y;
                    rbuf[4 * q + 2] += g * ww.z; rbuf[4 * q + 3] += g * ww.w;
                }
            }
        }
        #pragma unroll
        for (int d = 0; d < 64; d++) s_prev[pbase + d] = rbuf[d];
    }

    // ---- write final slots (guarded) ----
    if (valid) {
        float4* o = (float4*)(out + SLOTS_OFF + (b * NSLOT + s) * SDIM);
        #pragma unroll
        for (int q = 0; q < 16; q++)
            o[q] = make_float4(rbuf[4 * q], rbuf[4 * q + 1], rbuf[4 * q + 2], rbuf[4 * q + 3]);
    }

    // ---- free_act partial (per thread) ----
    float freeval = 0.0f;
    if (valid && s >= NKNOWN) {
        float sq = 0.0f;
        #pragma unroll
        for (int d = 0; d < 64; d++) sq += rbuf[d] * rbuf[d];
        freeval = sqrtf(sq) * (1.0f / (float)B_TOTAL);
    }

    // ---- head (reuse weight smem) + block-level free_act reduction ----
    __syncthreads();
    float* s_hw1  = sm;           // 18432 floats (overlaps s_whh+s_w1, dead now)
    float* s_hb1  = sm + 18432;   // 288
    float* s_hw2  = sm + 18720;   // 288
    float* s_hb2  = sm + 19008;   // 9
    float* s_free = sm + 19072;   // 23
    for (int i = tid; i < 18432 / 4; i += 384) ((float4*)s_hw1)[i] = ((const float4*)Wh1)[i];
    if (tid < 288) { s_hb1[tid] = bh1[tid]; s_hw2[tid] = Wh2[tid]; }
    if (tid >= 288 && tid < 297) s_hb2[tid - 288] = bh2[tid - 288];
    if (tid >= 320 && tid < 343) s_free[tid - 320] = 0.0f;
    __syncthreads();

    if (valid && s < NKNOWN) {
        int k = s;
        float ha[32];
        #pragma unroll
        for (int h = 0; h < 32; h++) ha[h] = s_hb1[k * 32 + h];
        #pragma unroll 2
        for (int d = 0; d < 64; d++) {
            float p = s_prev[pbase + d];
            const float4* w = (const float4*)(s_hw1 + k * 2048 + d * 32);
            #pragma unroll
            for (int q = 0; q < 8; q++) {
                float4 a = w[q];
                ha[4 * q + 0] += p * a.x; ha[4 * q + 1] += p * a.y;
                ha[4 * q + 2] += p * a.z; ha[4 * q + 3] += p * a.w;
            }
        }
        float a2 = s_hb2[k];
        #pragma unroll
        for (int h = 0; h < 32; h++) a2 += gelu_f(ha[h]) * s_hw2[k * 32 + h];
        out[PV_OFF + b * NKNOWN + k] = sigm_f(a2);
    } else if (valid && s >= NKNOWN) {
        atomicAdd(s_free + (s - NKNOWN), freeval);
    }
    __syncthreads();
    if (tid < NSLOT - NKNOWN) atomicAdd(out + FREE_OFF + tid, s_free[tid]);
}

// ================= launch =================
extern "C" void kernel_launch(void* const* d_in, const int* in_sizes, int n_in,
                              void* d_out, int out_size)
{
    const float* ws   = (const float*)d_in[0];
    const float* eps  = (const float*)d_in[1];
    const float* mu0  = (const float*)d_in[2];
    const float* sg0  = (const float*)d_in[3];
    const float* Wi   = (const float*)d_in[4];
    const float* bi   = (const float*)d_in[5];
    // d_in[6..9] = Wk, bk, Wq, bq : dead (attn == 1.0 exactly)
    const float* Wv   = (const float*)d_in[10];
    const float* bv   = (const float*)d_in[11];
    const float* Wih  = (const float*)d_in[12];
    const float* bih  = (const float*)d_in[13];
    const float* Whh  = (const float*)d_in[14];
    const float* bhh  = (const float*)d_in[15];
    const float* W1   = (const float*)d_in[16];
    const float* b1   = (const float*)d_in[17];
    const float* W2   = (const float*)d_in[18];
    const float* b2   = (const float*)d_in[19];
    const float* g_in = (const float*)d_in[20];
    const float* b_in = (const float*)d_in[21];
    // d_in[22..23] = g_sl, b_sl : dead
    const float* gm   = (const float*)d_in[24];
    const float* bm   = (const float*)d_in[25];
    const float* Wh1  = (const float*)d_in[26];
    const float* bh1  = (const float*)d_in[27];
    const float* Wh2  = (const float*)d_in[28];
    const float* bh2  = (const float*)d_in[29];
    float* out = (float*)d_out;

    size_t smemA = (size_t)SMEMA_FLOATS * sizeof(float);
    size_t smemB = (size_t)SMEMB_FLOATS * sizeof(float);
    cudaFuncSetAttribute(kA2, cudaFuncAttributeMaxDynamicSharedMemorySize, (int)smemA);
    cudaFuncSetAttribute(kB,  cudaFuncAttributeMaxDynamicSharedMemorySize, (int)smemB);

    int gridB = (B_TOTAL + GROUPS_B - 1) / GROUPS_B;   // 1366
    kA2<<<B_TOTAL / 8, 512, smemA>>>(ws, Wi, bi, g_in, b_in, Wv, bv, Wih, bih);
    kZ<<<1, 32>>>(out);
    kB<<<gridB, 384, smemB>>>(eps, mu0, sg0, Whh, bhh, W1, b1, W2, b2,
                              gm, bm, Wh1, bh1, Wh2, bh2, out);
}